// round 2
// baseline (speedup 1.0000x reference)
#include <cuda_runtime.h>
#include <math.h>

#define T_DEPTH 12
#define E_MSG   8192
#define H_DIM   256
#define V_VOCAB 800
#define B_ROOT  256
#define MAX_NB  8
#define M_TOTAL (T_DEPTH * E_MSG)
#define TILE_E  16

// Scratch (no cudaMalloc allowed): HU[i] = h[i] @ Ur, plus premultiplied embedding tables.
__device__ float g_HU[(size_t)(1 + M_TOTAL) * H_DIM];
__device__ float g_EWz0[V_VOCAB * H_DIM];  // embedding @ Wz[0:256]
__device__ float g_EWr [V_VOCAB * H_DIM];  // embedding @ Wr
__device__ float g_EWh0[V_VOCAB * H_DIM];  // embedding @ Wh[0:256]
__device__ float g_EWo0[V_VOCAB * H_DIM];  // embedding @ Wo[0:256]

__device__ __forceinline__ float sigmoidf_(float x) {
    return 1.0f / (1.0f + expf(-x));
}

// Zero pad rows: h[0][:] and HU[0][:]
__global__ void zero_kernel(float* __restrict__ h) {
    int j = threadIdx.x;
    h[j] = 0.0f;
    g_HU[j] = 0.0f;
}

// Premultiply embedding table by the four x-side weight blocks.
// grid = V_VOCAB blocks, 256 threads; thread j computes column j of 4 GEMVs.
__global__ void precompute_kernel(const float* __restrict__ emb,
                                  const float* __restrict__ Wz,
                                  const float* __restrict__ Wr,
                                  const float* __restrict__ Wh,
                                  const float* __restrict__ Wo) {
    __shared__ float se[H_DIM];
    int v = blockIdx.x;
    int j = threadIdx.x;
    se[j] = emb[v * H_DIM + j];
    __syncthreads();
    float az = 0.f, ar = 0.f, ah = 0.f, ao = 0.f;
    #pragma unroll 4
    for (int k = 0; k < H_DIM; k++) {
        float e = se[k];
        az += e * Wz[k * H_DIM + j];
        ar += e * Wr[k * H_DIM + j];
        ah += e * Wh[k * H_DIM + j];
        ao += e * Wo[k * H_DIM + j];
    }
    g_EWz0[v * H_DIM + j] = az;
    g_EWr [v * H_DIM + j] = ar;
    g_EWh0[v * H_DIM + j] = ah;
    g_EWo0[v * H_DIM + j] = ao;
}

// One depth of the tree-GRU scan. TILE_E messages per block, 256 threads,
// thread j owns output column j for all TILE_E messages.
__global__ __launch_bounds__(H_DIM) void depth_kernel(
    int t, float* __restrict__ h,
    const int* __restrict__ x_ids, const int* __restrict__ nei_idx,
    const float* __restrict__ Wz, const float* __restrict__ bz,
    const float* __restrict__ Ur, const float* __restrict__ bur,
    const float* __restrict__ Wh, const float* __restrict__ bh) {

    __shared__ float s_sumh[TILE_E][H_DIM];
    __shared__ float s_sg  [TILE_E][H_DIM];
    __shared__ float s_nh  [TILE_E][H_DIM];
    __shared__ int   s_xid [TILE_E];
    __shared__ int   s_nidx[TILE_E][MAX_NB];

    const int j    = threadIdx.x;
    const int e0   = blockIdx.x * TILE_E;
    const int base = 1 + t * E_MSG;

    if (j < TILE_E)
        s_xid[j] = x_ids[t * E_MSG + e0 + j];
    if (j < TILE_E * MAX_NB)
        s_nidx[j / MAX_NB][j % MAX_NB] = nei_idx[((size_t)(t * E_MSG + e0)) * MAX_NB + j];
    __syncthreads();

    // Phase 1: gather neighbors, compute sum_h and sum_gated per column.
    // sg_j = sum_n sigmoid(r1_j + HU[idx][j] + bur_j) * h[idx][j]  -- fully columnwise!
    const float burj = bur[j];
    for (int m = 0; m < TILE_E; m++) {
        float r1 = g_EWr[s_xid[m] * H_DIM + j];
        float sum_h = 0.f, sg = 0.f;
        #pragma unroll
        for (int n = 0; n < MAX_NB; n++) {
            int idx = s_nidx[m][n];   // warp-uniform
            if (idx != 0) {
                float hn = h[(size_t)idx * H_DIM + j];
                float hu = g_HU[(size_t)idx * H_DIM + j];
                sum_h += hn;
                sg += sigmoidf_(r1 + hu + burj) * hn;
            }
        }
        s_sumh[m][j] = sum_h;
        s_sg  [m][j] = sg;
    }
    __syncthreads();

    // Phase 2: the two remaining dense GEMMs: sum_h @ Wz1, sum_gated @ Wh1.
    float az[TILE_E], ah[TILE_E];
    #pragma unroll
    for (int m = 0; m < TILE_E; m++) { az[m] = 0.f; ah[m] = 0.f; }
    const float* Wz1 = Wz + H_DIM * H_DIM;   // rows 256..511 (sum_h part of concat)
    const float* Wh1 = Wh + H_DIM * H_DIM;
    for (int k = 0; k < H_DIM; k++) {
        float wz = Wz1[k * H_DIM + j];
        float wh = Wh1[k * H_DIM + j];
        #pragma unroll
        for (int m = 0; m < TILE_E; m++) {
            az[m] += s_sumh[m][k] * wz;
            ah[m] += s_sg  [m][k] * wh;
        }
    }

    // Phase 3: nonlinearities + combine, write new_h.
    const float bzj = bz[j], bhj = bh[j];
    for (int m = 0; m < TILE_E; m++) {
        int xid = s_xid[m];
        float z  = sigmoidf_(az[m] + g_EWz0[xid * H_DIM + j] + bzj);
        float ph = tanhf    (ah[m] + g_EWh0[xid * H_DIM + j] + bhj);
        float nh = (1.f - z) * s_sumh[m][j] + z * ph;
        h[(size_t)(base + e0 + m) * H_DIM + j] = nh;
        s_nh[m][j] = nh;
    }
    __syncthreads();

    // Phase 4: HU update: new_h @ Ur (memoized so later depths gather instead of GEMM).
    float au[TILE_E];
    #pragma unroll
    for (int m = 0; m < TILE_E; m++) au[m] = 0.f;
    for (int k = 0; k < H_DIM; k++) {
        float u = Ur[k * H_DIM + j];
        #pragma unroll
        for (int m = 0; m < TILE_E; m++) au[m] += s_nh[m][k] * u;
    }
    #pragma unroll
    for (int m = 0; m < TILE_E; m++)
        g_HU[(size_t)(base + e0 + m) * H_DIM + j] = au[m];
}

// Root aggregation: relu([emb[root_wid], sum_n h[root_nei]] @ Wo + bo)
__global__ void root_kernel(const float* __restrict__ h, float* __restrict__ out2,
                            const int* __restrict__ root_wid,
                            const int* __restrict__ root_nei,
                            const float* __restrict__ Wo,
                            const float* __restrict__ bo) {
    __shared__ float s_sum[H_DIM];
    int b = blockIdx.x, j = threadIdx.x;
    float sum = 0.f;
    #pragma unroll
    for (int n = 0; n < MAX_NB; n++) {
        int idx = root_nei[b * MAX_NB + n];
        if (idx != 0) sum += h[(size_t)idx * H_DIM + j];
    }
    s_sum[j] = sum;
    __syncthreads();
    float acc = bo[j] + g_EWo0[root_wid[b] * H_DIM + j];
    const float* Wo1 = Wo + H_DIM * H_DIM;
    #pragma unroll 4
    for (int k = 0; k < H_DIM; k++) acc += s_sum[k] * Wo1[k * H_DIM + j];
    out2[b * H_DIM + j] = fmaxf(acc, 0.f);
}

extern "C" void kernel_launch(void* const* d_in, const int* in_sizes, int n_in,
                              void* d_out, int out_size) {
    const int*   x_ids    = (const int*)  d_in[0];
    const int*   nei_idx  = (const int*)  d_in[1];
    const int*   root_wid = (const int*)  d_in[2];
    const int*   root_nei = (const int*)  d_in[3];
    const float* emb      = (const float*)d_in[4];
    const float* Wz       = (const float*)d_in[5];
    const float* bz       = (const float*)d_in[6];
    const float* Wr       = (const float*)d_in[7];  (void)Wr; // folded into g_EWr
    const float* Ur       = (const float*)d_in[8];
    const float* bur      = (const float*)d_in[9];
    const float* Wh       = (const float*)d_in[10];
    const float* bh       = (const float*)d_in[11];
    const float* Wo       = (const float*)d_in[12];
    const float* bo       = (const float*)d_in[13];

    float* h    = (float*)d_out;                         // [(1+M), H]
    float* out2 = h + (size_t)(1 + M_TOTAL) * H_DIM;     // [B, H]

    zero_kernel<<<1, H_DIM>>>(h);
    precompute_kernel<<<V_VOCAB, H_DIM>>>(emb, Wz, (const float*)d_in[7], Wh, Wo);
    for (int t = 0; t < T_DEPTH; t++) {
        depth_kernel<<<E_MSG / TILE_E, H_DIM>>>(t, h, x_ids, nei_idx,
                                                Wz, bz, Ur, bur, Wh, bh);
    }
    root_kernel<<<B_ROOT, H_DIM>>>(h, out2, root_wid, root_nei, Wo, bo);
}

// round 3
// speedup vs baseline: 1.0009x; 1.0009x over previous
#include <cuda_runtime.h>
#include <math.h>

#define T_DEPTH 12
#define E_MSG   8192
#define H_DIM   256
#define V_VOCAB 800
#define B_ROOT  256
#define MAX_NB  8
#define M_TOTAL (T_DEPTH * E_MSG)
#define TILE_E  16
#define SPITCH  20   // 16 m + 4 pad; 80B row stride (16B-aligned), 4-way write conflicts only

typedef unsigned long long ull;

// Scratch (no cudaMalloc allowed): HU[i] = h[i] @ Ur, plus premultiplied embedding tables.
__device__ float g_HU[(size_t)(1 + M_TOTAL) * H_DIM];
__device__ float g_EWz0[V_VOCAB * H_DIM];  // embedding @ Wz[0:256]
__device__ float g_EWr [V_VOCAB * H_DIM];  // embedding @ Wr
__device__ float g_EWh0[V_VOCAB * H_DIM];  // embedding @ Wh[0:256]
__device__ float g_EWo0[V_VOCAB * H_DIM];  // embedding @ Wo[0:256]

__device__ __forceinline__ float sigmoidf_(float x) {
    return 1.0f / (1.0f + expf(-x));
}

// ---- packed f32x2 helpers (Blackwell FFMA2 path) ----
__device__ __forceinline__ ull pack2(float w) {
    ull r;
    unsigned int wu = __float_as_uint(w);
    asm("mov.b64 %0, {%1, %1};" : "=l"(r) : "r"(wu));
    return r;
}
__device__ __forceinline__ ull fma2(ull a, ull b, ull c) {
    ull d;
    asm("fma.rn.f32x2 %0, %1, %2, %3;" : "=l"(d) : "l"(a), "l"(b), "l"(c));
    return d;
}
__device__ __forceinline__ void unpack2(ull v, float& lo, float& hi) {
    asm("mov.b64 {%0, %1}, %2;" : "=f"(lo), "=f"(hi) : "l"(v));
}

// Zero pad rows: h[0][:] and HU[0][:]
__global__ void zero_kernel(float* __restrict__ h) {
    int j = threadIdx.x;
    h[j] = 0.0f;
    g_HU[j] = 0.0f;
}

// Premultiply embedding table by the four x-side weight blocks.
__global__ void precompute_kernel(const float* __restrict__ emb,
                                  const float* __restrict__ Wz,
                                  const float* __restrict__ Wr,
                                  const float* __restrict__ Wh,
                                  const float* __restrict__ Wo) {
    __shared__ float se[H_DIM];
    int v = blockIdx.x;
    int j = threadIdx.x;
    se[j] = emb[v * H_DIM + j];
    __syncthreads();
    float az = 0.f, ar = 0.f, ah = 0.f, ao = 0.f;
    #pragma unroll 4
    for (int k = 0; k < H_DIM; k++) {
        float e = se[k];
        az += e * Wz[k * H_DIM + j];
        ar += e * Wr[k * H_DIM + j];
        ah += e * Wh[k * H_DIM + j];
        ao += e * Wo[k * H_DIM + j];
    }
    g_EWz0[v * H_DIM + j] = az;
    g_EWr [v * H_DIM + j] = ar;
    g_EWh0[v * H_DIM + j] = ah;
    g_EWo0[v * H_DIM + j] = ao;
}

// One depth of the tree-GRU scan. TILE_E messages per block, 256 threads,
// thread j owns output column j. GEMMs run as packed f32x2 FMA with
// transposed shared staging ([k][m]) so one LDS.128 feeds 2 FFMA2.
__global__ __launch_bounds__(H_DIM) void depth_kernel(
    int t, float* __restrict__ h,
    const int* __restrict__ x_ids, const int* __restrict__ nei_idx,
    const float* __restrict__ Wz, const float* __restrict__ bz,
    const float* __restrict__ Ur, const float* __restrict__ bur,
    const float* __restrict__ Wh, const float* __restrict__ bh) {

    __shared__ __align__(16) float s_A[H_DIM][SPITCH];  // sum_h, transposed [k][m]
    __shared__ __align__(16) float s_B[H_DIM][SPITCH];  // sum_gated, then new_h
    __shared__ int s_xid [TILE_E];
    __shared__ int s_nidx[TILE_E][MAX_NB];

    const int j    = threadIdx.x;
    const int e0   = blockIdx.x * TILE_E;
    const int base = 1 + t * E_MSG;

    if (j < TILE_E)
        s_xid[j] = x_ids[t * E_MSG + e0 + j];
    if (j < TILE_E * MAX_NB)
        s_nidx[j / MAX_NB][j % MAX_NB] = nei_idx[((size_t)(t * E_MSG + e0)) * MAX_NB + j];
    __syncthreads();

    // ---- Phase 1: neighbor gather; columnwise sum_h and sum_gated ----
    const float burj = bur[j];
    #pragma unroll 2
    for (int m = 0; m < TILE_E; m++) {
        float r1 = g_EWr[s_xid[m] * H_DIM + j];
        float sum_h = 0.f, sg = 0.f;
        #pragma unroll
        for (int n = 0; n < MAX_NB; n++) {
            int idx = s_nidx[m][n];   // warp-uniform
            if (idx != 0) {
                float hn = h[(size_t)idx * H_DIM + j];
                float hu = g_HU[(size_t)idx * H_DIM + j];
                sum_h += hn;
                sg = fmaf(sigmoidf_(r1 + hu + burj), hn, sg);
            }
        }
        s_A[j][m] = sum_h;
        s_B[j][m] = sg;
    }
    __syncthreads();

    // ---- Phase 2: sum_h @ Wz1 and sum_gated @ Wh1, packed f32x2 ----
    ull az[TILE_E / 2], ah[TILE_E / 2];
    #pragma unroll
    for (int p = 0; p < TILE_E / 2; p++) { az[p] = 0ull; ah[p] = 0ull; }
    const float* Wz1 = Wz + H_DIM * H_DIM + j;
    const float* Wh1 = Wh + H_DIM * H_DIM + j;
    #pragma unroll 4
    for (int k = 0; k < H_DIM; k++) {
        ull wz2 = pack2(Wz1[(size_t)k * H_DIM]);
        ull wh2 = pack2(Wh1[(size_t)k * H_DIM]);
        const ulonglong2* pa = reinterpret_cast<const ulonglong2*>(s_A[k]);
        const ulonglong2* pb = reinterpret_cast<const ulonglong2*>(s_B[k]);
        #pragma unroll
        for (int q = 0; q < TILE_E / 4; q++) {
            ulonglong2 a = pa[q];
            ulonglong2 b = pb[q];
            az[2*q]   = fma2(a.x, wz2, az[2*q]);
            az[2*q+1] = fma2(a.y, wz2, az[2*q+1]);
            ah[2*q]   = fma2(b.x, wh2, ah[2*q]);
            ah[2*q+1] = fma2(b.y, wh2, ah[2*q+1]);
        }
    }
    __syncthreads();   // all reads of s_B (sg) done before it is overwritten with new_h

    // ---- Phase 3: nonlinearities, write new_h ----
    const float bzj = bz[j], bhj = bh[j];
    #pragma unroll
    for (int p = 0; p < TILE_E / 2; p++) {
        float azv[2], ahv[2];
        unpack2(az[p], azv[0], azv[1]);
        unpack2(ah[p], ahv[0], ahv[1]);
        #pragma unroll
        for (int u = 0; u < 2; u++) {
            int m = 2 * p + u;
            int xid = s_xid[m];
            float z  = sigmoidf_(azv[u] + g_EWz0[xid * H_DIM + j] + bzj);
            float ph = tanhf    (ahv[u] + g_EWh0[xid * H_DIM + j] + bhj);
            float nh = (1.f - z) * s_A[j][m] + z * ph;
            h[(size_t)(base + e0 + m) * H_DIM + j] = nh;
            s_B[j][m] = nh;
        }
    }
    __syncthreads();

    // ---- Phase 4: HU memo update: new_h @ Ur, packed f32x2 ----
    ull au[TILE_E / 2];
    #pragma unroll
    for (int p = 0; p < TILE_E / 2; p++) au[p] = 0ull;
    const float* Urj = Ur + j;
    #pragma unroll 4
    for (int k = 0; k < H_DIM; k++) {
        ull u2 = pack2(Urj[(size_t)k * H_DIM]);
        const ulonglong2* pb = reinterpret_cast<const ulonglong2*>(s_B[k]);
        #pragma unroll
        for (int q = 0; q < TILE_E / 4; q++) {
            ulonglong2 b = pb[q];
            au[2*q]   = fma2(b.x, u2, au[2*q]);
            au[2*q+1] = fma2(b.y, u2, au[2*q+1]);
        }
    }
    #pragma unroll
    for (int p = 0; p < TILE_E / 2; p++) {
        float lo, hi;
        unpack2(au[p], lo, hi);
        g_HU[(size_t)(base + e0 + 2*p    ) * H_DIM + j] = lo;
        g_HU[(size_t)(base + e0 + 2*p + 1) * H_DIM + j] = hi;
    }
}

// Root aggregation: relu([emb[root_wid], sum_n h[root_nei]] @ Wo + bo)
__global__ void root_kernel(const float* __restrict__ h, float* __restrict__ out2,
                            const int* __restrict__ root_wid,
                            const int* __restrict__ root_nei,
                            const float* __restrict__ Wo,
                            const float* __restrict__ bo) {
    __shared__ float s_sum[H_DIM];
    int b = blockIdx.x, j = threadIdx.x;
    float sum = 0.f;
    #pragma unroll
    for (int n = 0; n < MAX_NB; n++) {
        int idx = root_nei[b * MAX_NB + n];
        if (idx != 0) sum += h[(size_t)idx * H_DIM + j];
    }
    s_sum[j] = sum;
    __syncthreads();
    float acc = bo[j] + g_EWo0[root_wid[b] * H_DIM + j];
    const float* Wo1 = Wo + H_DIM * H_DIM;
    #pragma unroll 4
    for (int k = 0; k < H_DIM; k++) acc += s_sum[k] * Wo1[k * H_DIM + j];
    out2[b * H_DIM + j] = fmaxf(acc, 0.f);
}

extern "C" void kernel_launch(void* const* d_in, const int* in_sizes, int n_in,
                              void* d_out, int out_size) {
    const int*   x_ids    = (const int*)  d_in[0];
    const int*   nei_idx  = (const int*)  d_in[1];
    const int*   root_wid = (const int*)  d_in[2];
    const int*   root_nei = (const int*)  d_in[3];
    const float* emb      = (const float*)d_in[4];
    const float* Wz       = (const float*)d_in[5];
    const float* bz       = (const float*)d_in[6];
    const float* Wr       = (const float*)d_in[7];
    const float* Ur       = (const float*)d_in[8];
    const float* bur      = (const float*)d_in[9];
    const float* Wh       = (const float*)d_in[10];
    const float* bh       = (const float*)d_in[11];
    const float* Wo       = (const float*)d_in[12];
    const float* bo       = (const float*)d_in[13];

    float* h    = (float*)d_out;                         // [(1+M), H]
    float* out2 = h + (size_t)(1 + M_TOTAL) * H_DIM;     // [B, H]

    zero_kernel<<<1, H_DIM>>>(h);
    precompute_kernel<<<V_VOCAB, H_DIM>>>(emb, Wz, Wr, Wh, Wo);
    for (int t = 0; t < T_DEPTH; t++) {
        depth_kernel<<<E_MSG / TILE_E, H_DIM>>>(t, h, x_ids, nei_idx,
                                                Wz, bz, Ur, bur, Wh, bh);
    }
    root_kernel<<<B_ROOT, H_DIM>>>(h, out2, root_wid, root_nei, Wo, bo);
}

// round 4
// speedup vs baseline: 1.5720x; 1.5706x over previous
#include <cuda_runtime.h>
#include <math.h>

#define T_DEPTH 12
#define E_MSG   8192
#define H_DIM   256
#define V_VOCAB 800
#define B_ROOT  256
#define MAX_NB  8
#define M_TOTAL (T_DEPTH * E_MSG)

#define BM 64
#define BN 64
#define BK 16

typedef unsigned long long ull;

// Scratch (no cudaMalloc): HU memo, premultiplied embedding tables, per-depth staging.
__device__ float g_HU[(size_t)(1 + M_TOTAL) * H_DIM];
__device__ float g_EWz0[V_VOCAB * H_DIM];
__device__ float g_EWr [V_VOCAB * H_DIM];
__device__ float g_EWh0[V_VOCAB * H_DIM];
__device__ float g_EWo0[V_VOCAB * H_DIM];
__device__ float g_sumh[(size_t)E_MSG * H_DIM];
__device__ float g_sg  [(size_t)E_MSG * H_DIM];

__device__ __forceinline__ float sigmoidf_(float x) {
    return 1.0f / (1.0f + expf(-x));
}

// ---- packed f32x2 helpers ----
__device__ __forceinline__ ull pack2(float w) {
    ull r;
    unsigned int wu = __float_as_uint(w);
    asm("mov.b64 %0, {%1, %1};" : "=l"(r) : "r"(wu));
    return r;
}
__device__ __forceinline__ ull fma2(ull a, ull b, ull c) {
    ull d;
    asm("fma.rn.f32x2 %0, %1, %2, %3;" : "=l"(d) : "l"(a), "l"(b), "l"(c));
    return d;
}
__device__ __forceinline__ void unpack2(ull v, float& lo, float& hi) {
    asm("mov.b64 {%0, %1}, %2;" : "=f"(lo), "=f"(hi) : "l"(v));
}

__global__ void zero_kernel(float* __restrict__ h) {
    int j = threadIdx.x;
    h[j] = 0.0f;
    g_HU[j] = 0.0f;
}

// Premultiply embedding by the four x-side weight blocks (V=800 rows only).
__global__ void precompute_kernel(const float* __restrict__ emb,
                                  const float* __restrict__ Wz,
                                  const float* __restrict__ Wr,
                                  const float* __restrict__ Wh,
                                  const float* __restrict__ Wo) {
    __shared__ float se[H_DIM];
    int v = blockIdx.x;
    int j = threadIdx.x;
    se[j] = emb[v * H_DIM + j];
    __syncthreads();
    float az = 0.f, ar = 0.f, ah = 0.f, ao = 0.f;
    #pragma unroll 4
    for (int k = 0; k < H_DIM; k++) {
        float e = se[k];
        az += e * Wz[k * H_DIM + j];
        ar += e * Wr[k * H_DIM + j];
        ah += e * Wh[k * H_DIM + j];
        ao += e * Wo[k * H_DIM + j];
    }
    g_EWz0[v * H_DIM + j] = az;
    g_EWr [v * H_DIM + j] = ar;
    g_EWh0[v * H_DIM + j] = ah;
    g_EWo0[v * H_DIM + j] = ao;
}

// Phase A: neighbor gather. One block per message; thread j = column j.
// sum_gated_j = sum_n sigmoid(r1_j + HU[idx][j] + bur_j) * h[idx][j]
__global__ __launch_bounds__(H_DIM) void gather_kernel(
    int t, const float* __restrict__ h,
    const int* __restrict__ x_ids, const int* __restrict__ nei_idx,
    const float* __restrict__ bur) {

    __shared__ int s_nidx[MAX_NB];
    const int e = blockIdx.x;
    const int j = threadIdx.x;

    if (j < MAX_NB)
        s_nidx[j] = nei_idx[((size_t)(t * E_MSG + e)) * MAX_NB + j];
    __syncthreads();

    const int xid = x_ids[t * E_MSG + e];   // broadcast load
    const float r1b = g_EWr[xid * H_DIM + j] + bur[j];

    float sum_h = 0.f, sg = 0.f;
    #pragma unroll
    for (int n = 0; n < MAX_NB; n++) {
        int idx = s_nidx[n];   // block-uniform
        if (idx != 0) {
            float hn = h[(size_t)idx * H_DIM + j];
            float hu = g_HU[(size_t)idx * H_DIM + j];
            sum_h += hn;
            sg = fmaf(sigmoidf_(r1b + hu), hn, sg);
        }
    }
    g_sumh[(size_t)e * H_DIM + j] = sum_h;
    g_sg  [(size_t)e * H_DIM + j] = sg;
}

// Phase B: dual tiled GEMM (sum_h@Wz1, sg@Wh1) + fused GRU epilogue -> writes h.
// BM=64 x BN=64 tile, 256 threads, 4x4 register tile per thread, FFMA2 accum.
__global__ __launch_bounds__(256) void gemm_epi_kernel(
    int t, float* __restrict__ h,
    const int* __restrict__ x_ids,
    const float* __restrict__ Wz, const float* __restrict__ bz,
    const float* __restrict__ Wh, const float* __restrict__ bh) {

    __shared__ float sA1[BK][BM];   // sum_h, [k][m]
    __shared__ float sA2[BK][BM];   // sg
    __shared__ float sB1[BK][BN];   // Wz1
    __shared__ float sB2[BK][BN];   // Wh1

    const int tid = threadIdx.x;
    const int m0  = blockIdx.x * BM;
    const int n0  = blockIdx.y * BN;
    const int base = 1 + t * E_MSG;

    // load mapping
    const int tm  = tid >> 2;          // 0..63 (A row)
    const int tk4 = (tid & 3) * 4;     // A col group
    const int bkr = tid >> 4;          // 0..15 (B row)
    const int bn4 = (tid & 15) * 4;    // B col group
    // compute mapping (16x16 thread grid)
    const int mo = (tid & 15) * 4;
    const int no = (tid >> 4) * 4;

    const float* Wz1 = Wz + (size_t)H_DIM * H_DIM;
    const float* Wh1 = Wh + (size_t)H_DIM * H_DIM;

    ull az[4][2], ah[4][2];
    #pragma unroll
    for (int i = 0; i < 4; i++)
        #pragma unroll
        for (int p = 0; p < 2; p++) { az[i][p] = 0ull; ah[i][p] = 0ull; }

    for (int k0 = 0; k0 < H_DIM; k0 += BK) {
        float4 a1 = *(const float4*)&g_sumh[(size_t)(m0 + tm) * H_DIM + k0 + tk4];
        float4 a2 = *(const float4*)&g_sg  [(size_t)(m0 + tm) * H_DIM + k0 + tk4];
        float4 b1 = *(const float4*)&Wz1[(size_t)(k0 + bkr) * H_DIM + n0 + bn4];
        float4 b2 = *(const float4*)&Wh1[(size_t)(k0 + bkr) * H_DIM + n0 + bn4];
        __syncthreads();
        sA1[tk4 + 0][tm] = a1.x; sA1[tk4 + 1][tm] = a1.y;
        sA1[tk4 + 2][tm] = a1.z; sA1[tk4 + 3][tm] = a1.w;
        sA2[tk4 + 0][tm] = a2.x; sA2[tk4 + 1][tm] = a2.y;
        sA2[tk4 + 2][tm] = a2.z; sA2[tk4 + 3][tm] = a2.w;
        *(float4*)&sB1[bkr][bn4] = b1;
        *(float4*)&sB2[bkr][bn4] = b2;
        __syncthreads();
        #pragma unroll
        for (int kk = 0; kk < BK; kk++) {
            float4 av1 = *(const float4*)&sA1[kk][mo];
            float4 av2 = *(const float4*)&sA2[kk][mo];
            ulonglong2 bv1 = *(const ulonglong2*)&sB1[kk][no];
            ulonglong2 bv2 = *(const ulonglong2*)&sB2[kk][no];
            const float a1f[4] = {av1.x, av1.y, av1.z, av1.w};
            const float a2f[4] = {av2.x, av2.y, av2.z, av2.w};
            #pragma unroll
            for (int i = 0; i < 4; i++) {
                ull ap1 = pack2(a1f[i]);
                ull ap2 = pack2(a2f[i]);
                az[i][0] = fma2(ap1, bv1.x, az[i][0]);
                az[i][1] = fma2(ap1, bv1.y, az[i][1]);
                ah[i][0] = fma2(ap2, bv2.x, ah[i][0]);
                ah[i][1] = fma2(ap2, bv2.y, ah[i][1]);
            }
        }
    }

    // Fused GRU epilogue: z/r nonlinearities, combine, write new_h.
    #pragma unroll
    for (int i = 0; i < 4; i++) {
        const int m = m0 + mo + i;
        const int xid = x_ids[t * E_MSG + m];
        const float* ewz = &g_EWz0[(size_t)xid * H_DIM];
        const float* ewh = &g_EWh0[(size_t)xid * H_DIM];
        #pragma unroll
        for (int p = 0; p < 2; p++) {
            float azv[2], ahv[2];
            unpack2(az[i][p], azv[0], azv[1]);
            unpack2(ah[i][p], ahv[0], ahv[1]);
            #pragma unroll
            for (int u = 0; u < 2; u++) {
                const int n = n0 + no + 2 * p + u;
                float z  = sigmoidf_(azv[u] + ewz[n] + bz[n]);
                float ph = tanhf    (ahv[u] + ewh[n] + bh[n]);
                float sh = g_sumh[(size_t)m * H_DIM + n];
                h[(size_t)(base + m) * H_DIM + n] = (1.f - z) * sh + z * ph;
            }
        }
    }
}

// Phase C: HU memo GEMM: g_HU[row] = new_h[row] @ Ur for this depth's rows.
__global__ __launch_bounds__(256) void hu_gemm_kernel(
    int t, const float* __restrict__ h, const float* __restrict__ Ur) {

    __shared__ float sA[BK][BM];
    __shared__ float sB[BK][BN];

    const int tid = threadIdx.x;
    const int m0  = blockIdx.x * BM;
    const int n0  = blockIdx.y * BN;
    const int base = 1 + t * E_MSG;

    const int tm  = tid >> 2;
    const int tk4 = (tid & 3) * 4;
    const int bkr = tid >> 4;
    const int bn4 = (tid & 15) * 4;
    const int mo = (tid & 15) * 4;
    const int no = (tid >> 4) * 4;

    ull acc[4][2];
    #pragma unroll
    for (int i = 0; i < 4; i++) { acc[i][0] = 0ull; acc[i][1] = 0ull; }

    for (int k0 = 0; k0 < H_DIM; k0 += BK) {
        float4 a = *(const float4*)&h[(size_t)(base + m0 + tm) * H_DIM + k0 + tk4];
        float4 b = *(const float4*)&Ur[(size_t)(k0 + bkr) * H_DIM + n0 + bn4];
        __syncthreads();
        sA[tk4 + 0][tm] = a.x; sA[tk4 + 1][tm] = a.y;
        sA[tk4 + 2][tm] = a.z; sA[tk4 + 3][tm] = a.w;
        *(float4*)&sB[bkr][bn4] = b;
        __syncthreads();
        #pragma unroll
        for (int kk = 0; kk < BK; kk++) {
            float4 av = *(const float4*)&sA[kk][mo];
            ulonglong2 bv = *(const ulonglong2*)&sB[kk][no];
            const float af[4] = {av.x, av.y, av.z, av.w};
            #pragma unroll
            for (int i = 0; i < 4; i++) {
                ull ap = pack2(af[i]);
                acc[i][0] = fma2(ap, bv.x, acc[i][0]);
                acc[i][1] = fma2(ap, bv.y, acc[i][1]);
            }
        }
    }

    #pragma unroll
    for (int i = 0; i < 4; i++) {
        const int m = m0 + mo + i;
        #pragma unroll
        for (int p = 0; p < 2; p++) {
            float lo, hi;
            unpack2(acc[i][p], lo, hi);
            const int n = n0 + no + 2 * p;
            g_HU[(size_t)(base + m) * H_DIM + n]     = lo;
            g_HU[(size_t)(base + m) * H_DIM + n + 1] = hi;
        }
    }
}

// Root aggregation: relu([emb[root_wid], sum_n h[root_nei]] @ Wo + bo)
__global__ void root_kernel(const float* __restrict__ h, float* __restrict__ out2,
                            const int* __restrict__ root_wid,
                            const int* __restrict__ root_nei,
                            const float* __restrict__ Wo,
                            const float* __restrict__ bo) {
    __shared__ float s_sum[H_DIM];
    int b = blockIdx.x, j = threadIdx.x;
    float sum = 0.f;
    #pragma unroll
    for (int n = 0; n < MAX_NB; n++) {
        int idx = root_nei[b * MAX_NB + n];
        if (idx != 0) sum += h[(size_t)idx * H_DIM + j];
    }
    s_sum[j] = sum;
    __syncthreads();
    float acc = bo[j] + g_EWo0[root_wid[b] * H_DIM + j];
    const float* Wo1 = Wo + H_DIM * H_DIM;
    #pragma unroll 4
    for (int k = 0; k < H_DIM; k++) acc += s_sum[k] * Wo1[k * H_DIM + j];
    out2[b * H_DIM + j] = fmaxf(acc, 0.f);
}

extern "C" void kernel_launch(void* const* d_in, const int* in_sizes, int n_in,
                              void* d_out, int out_size) {
    const int*   x_ids    = (const int*)  d_in[0];
    const int*   nei_idx  = (const int*)  d_in[1];
    const int*   root_wid = (const int*)  d_in[2];
    const int*   root_nei = (const int*)  d_in[3];
    const float* emb      = (const float*)d_in[4];
    const float* Wz       = (const float*)d_in[5];
    const float* bz       = (const float*)d_in[6];
    const float* Wr       = (const float*)d_in[7];
    const float* Ur       = (const float*)d_in[8];
    const float* bur      = (const float*)d_in[9];
    const float* Wh       = (const float*)d_in[10];
    const float* bh       = (const float*)d_in[11];
    const float* Wo       = (const float*)d_in[12];
    const float* bo       = (const float*)d_in[13];

    float* h    = (float*)d_out;                         // [(1+M), H]
    float* out2 = h + (size_t)(1 + M_TOTAL) * H_DIM;     // [B, H]

    zero_kernel<<<1, H_DIM>>>(h);
    precompute_kernel<<<V_VOCAB, H_DIM>>>(emb, Wz, Wr, Wh, Wo);

    dim3 ggrid(E_MSG / BM, H_DIM / BN);
    for (int t = 0; t < T_DEPTH; t++) {
        gather_kernel<<<E_MSG, H_DIM>>>(t, h, x_ids, nei_idx, bur);
        gemm_epi_kernel<<<ggrid, 256>>>(t, h, x_ids, Wz, bz, Wh, bh);
        hu_gemm_kernel<<<ggrid, 256>>>(t, h, Ur);
    }
    root_kernel<<<B_ROOT, H_DIM>>>(h, out2, root_wid, root_nei, Wo, bo);
}

// round 5
// speedup vs baseline: 1.9279x; 1.2264x over previous
#include <cuda_runtime.h>
#include <math.h>

#define T_DEPTH 12
#define E_MSG   8192
#define H_DIM   256
#define V_VOCAB 800
#define B_ROOT  256
#define MAX_NB  8
#define M_TOTAL (T_DEPTH * E_MSG)

// GEMM tiling
#define BLK_M 128
#define BLK_N 64
#define BLK_K 32
#define GEMM_THREADS 128
#define PA 36   // sA pitch (floats): bank = (4m+k)%32, conflict-free frag reads
#define PB 72   // sB pitch (floats): bank = (8k+n)%32, conflict-free frag reads

typedef unsigned long long ull;

// Scratch (no cudaMalloc allowed)
__device__ float g_HU[(size_t)(1 + M_TOTAL) * H_DIM];
__device__ float g_EWz0[V_VOCAB * H_DIM];
__device__ float g_EWr [V_VOCAB * H_DIM];
__device__ float g_EWh0[V_VOCAB * H_DIM];
__device__ float g_EWo0[V_VOCAB * H_DIM];
__device__ float g_sumh[(size_t)E_MSG * H_DIM];
__device__ float g_sg  [(size_t)E_MSG * H_DIM];
__device__ float g_az  [(size_t)E_MSG * H_DIM];
__device__ float g_ah  [(size_t)E_MSG * H_DIM];
// tf32 hi/lo split of the three depth-invariant B matrices: [0]=Wz1 [1]=Wh1 [2]=Ur
__device__ float g_Bhi[3 * H_DIM * H_DIM];
__device__ float g_Blo[3 * H_DIM * H_DIM];

__device__ __forceinline__ float sigmoidf_(float x) {
    return 1.0f / (1.0f + expf(-x));
}
__device__ __forceinline__ unsigned int tf32_rna(float a) {
    unsigned int r;
    asm("cvt.rna.tf32.f32 %0, %1;" : "=r"(r) : "f"(a));
    return r;
}
__device__ __forceinline__ void mma_tf32(float& d0, float& d1, float& d2, float& d3,
                                         unsigned int a0, unsigned int a1,
                                         unsigned int a2, unsigned int a3,
                                         unsigned int b0, unsigned int b1) {
    asm volatile(
        "mma.sync.aligned.m16n8k8.row.col.f32.tf32.tf32.f32 "
        "{%0,%1,%2,%3}, {%4,%5,%6,%7}, {%8,%9}, {%0,%1,%2,%3};"
        : "+f"(d0), "+f"(d1), "+f"(d2), "+f"(d3)
        : "r"(a0), "r"(a1), "r"(a2), "r"(a3), "r"(b0), "r"(b1));
}

__global__ void zero_kernel(float* __restrict__ h) {
    int j = threadIdx.x;
    h[j] = 0.0f;
    g_HU[j] = 0.0f;
}

// Premultiply embedding by the four x-side weight blocks (V=800 rows only).
__global__ void precompute_kernel(const float* __restrict__ emb,
                                  const float* __restrict__ Wz,
                                  const float* __restrict__ Wr,
                                  const float* __restrict__ Wh,
                                  const float* __restrict__ Wo) {
    __shared__ float se[H_DIM];
    int v = blockIdx.x;
    int j = threadIdx.x;
    se[j] = emb[v * H_DIM + j];
    __syncthreads();
    float az = 0.f, ar = 0.f, ah = 0.f, ao = 0.f;
    #pragma unroll 4
    for (int k = 0; k < H_DIM; k++) {
        float e = se[k];
        az += e * Wz[k * H_DIM + j];
        ar += e * Wr[k * H_DIM + j];
        ah += e * Wh[k * H_DIM + j];
        ao += e * Wo[k * H_DIM + j];
    }
    g_EWz0[v * H_DIM + j] = az;
    g_EWr [v * H_DIM + j] = ar;
    g_EWh0[v * H_DIM + j] = ah;
    g_EWo0[v * H_DIM + j] = ao;
}

// Split B matrices (Wz1, Wh1, Ur) into tf32 hi + tf32(lo) tables, [k][n] layout.
__global__ void bsplit_kernel(const float* __restrict__ Wz,
                              const float* __restrict__ Wh,
                              const float* __restrict__ Ur) {
    int sel = blockIdx.x >> 8;          // 0..2
    int row = blockIdx.x & 255;
    int j   = threadIdx.x;
    const float* src = (sel == 0) ? (Wz + H_DIM * H_DIM)
                     : (sel == 1) ? (Wh + H_DIM * H_DIM) : Ur;
    float w = src[(size_t)row * H_DIM + j];
    unsigned int hi = tf32_rna(w);
    float hif = __uint_as_float(hi);
    unsigned int lo = tf32_rna(w - hif);
    size_t o = (size_t)sel * H_DIM * H_DIM + (size_t)row * H_DIM + j;
    g_Bhi[o] = hif;
    g_Blo[o] = __uint_as_float(lo);
}

// Phase A: neighbor gather. One block per message; thread j = column j.
__global__ __launch_bounds__(H_DIM) void gather_kernel(
    int t, const float* __restrict__ h,
    const int* __restrict__ x_ids, const int* __restrict__ nei_idx,
    const float* __restrict__ bur) {

    __shared__ int s_nidx[MAX_NB];
    const int e = blockIdx.x;
    const int j = threadIdx.x;

    if (j < MAX_NB)
        s_nidx[j] = nei_idx[((size_t)(t * E_MSG + e)) * MAX_NB + j];
    __syncthreads();

    const int xid = x_ids[t * E_MSG + e];
    const float r1b = g_EWr[xid * H_DIM + j] + bur[j];

    float sum_h = 0.f, sg = 0.f;
    #pragma unroll
    for (int n = 0; n < MAX_NB; n++) {
        int idx = s_nidx[n];
        if (idx != 0) {
            float hn = h[(size_t)idx * H_DIM + j];
            float hu = g_HU[(size_t)idx * H_DIM + j];
            sum_h += hn;
            sg = fmaf(sigmoidf_(r1b + hu), hn, sg);
        }
    }
    g_sumh[(size_t)e * H_DIM + j] = sum_h;
    g_sg  [(size_t)e * H_DIM + j] = sg;
}

// Tensor-core GEMM: C = A[8192 x 256] @ B[256 x 256] via 3xTF32 mma.sync.
// blockIdx.z selects (A,C,bsel) pair. Block tile 128x64, 4 warps of 64x32.
__global__ __launch_bounds__(GEMM_THREADS) void mma_gemm_kernel(
    const float* __restrict__ A0, float* __restrict__ C0, int bsel0,
    const float* __restrict__ A1, float* __restrict__ C1, int bsel1) {

    __shared__ float sA  [BLK_M * PA];
    __shared__ float sBhi[BLK_K * PB];
    __shared__ float sBlo[BLK_K * PB];

    const float* A = (blockIdx.z == 0) ? A0 : A1;
    float*       C = (blockIdx.z == 0) ? C0 : C1;
    const int  bsel = (blockIdx.z == 0) ? bsel0 : bsel1;
    const float* Bhi = g_Bhi + (size_t)bsel * H_DIM * H_DIM;
    const float* Blo = g_Blo + (size_t)bsel * H_DIM * H_DIM;

    const int tid  = threadIdx.x;
    const int lane = tid & 31;
    const int warp = tid >> 5;
    const int wm   = (warp & 1) * 64;   // warp M origin in tile
    const int wn   = (warp >> 1) * 32;  // warp N origin in tile
    const int g    = lane >> 2;
    const int tig  = lane & 3;

    const int m0 = blockIdx.x * BLK_M;
    const int n0 = blockIdx.y * BLK_N;

    float acc[4][4][4];   // [mfrag][nfrag][c0..c3]
    #pragma unroll
    for (int i = 0; i < 4; i++)
        #pragma unroll
        for (int jn = 0; jn < 4; jn++)
            #pragma unroll
            for (int c = 0; c < 4; c++) acc[i][jn][c] = 0.f;

    for (int kb = 0; kb < H_DIM; kb += BLK_K) {
        // Stage A: one row per thread, 32 floats (8 float4).
        {
            const float* ar = A + (size_t)(m0 + tid) * H_DIM + kb;
            #pragma unroll
            for (int c = 0; c < 8; c++) {
                float4 v = *(const float4*)(ar + 4 * c);
                *(float4*)&sA[tid * PA + 4 * c] = v;
            }
        }
        // Stage B hi/lo: 32x64 each; thread covers 4 float4.
        {
            const int nn = (tid & 15) * 4;
            #pragma unroll
            for (int p = 0; p < 4; p++) {
                const int kk = p * 8 + (tid >> 4);
                size_t go = (size_t)(kb + kk) * H_DIM + n0 + nn;
                *(float4*)&sBhi[kk * PB + nn] = *(const float4*)(Bhi + go);
                *(float4*)&sBlo[kk * PB + nn] = *(const float4*)(Blo + go);
            }
        }
        __syncthreads();

        #pragma unroll
        for (int ks = 0; ks < 4; ks++) {
            const int kc = ks * 8;
            // A fragments (hi + residual lo), 4 m-frags.
            unsigned int ahi[4][4], alo[4][4];
            #pragma unroll
            for (int mf = 0; mf < 4; mf++) {
                const int r0 = wm + mf * 16 + g;
                float a0 = sA[(r0    ) * PA + kc + tig    ];
                float a1 = sA[(r0 + 8) * PA + kc + tig    ];
                float a2 = sA[(r0    ) * PA + kc + tig + 4];
                float a3 = sA[(r0 + 8) * PA + kc + tig + 4];
                ahi[mf][0] = tf32_rna(a0); alo[mf][0] = tf32_rna(a0 - __uint_as_float(ahi[mf][0]));
                ahi[mf][1] = tf32_rna(a1); alo[mf][1] = tf32_rna(a1 - __uint_as_float(ahi[mf][1]));
                ahi[mf][2] = tf32_rna(a2); alo[mf][2] = tf32_rna(a2 - __uint_as_float(ahi[mf][2]));
                ahi[mf][3] = tf32_rna(a3); alo[mf][3] = tf32_rna(a3 - __uint_as_float(ahi[mf][3]));
            }
            // B fragments, 4 n-frags.
            unsigned int bhi[4][2], blo[4][2];
            #pragma unroll
            for (int nf = 0; nf < 4; nf++) {
                const int cc = wn + nf * 8 + g;
                bhi[nf][0] = __float_as_uint(sBhi[(kc + tig    ) * PB + cc]);
                bhi[nf][1] = __float_as_uint(sBhi[(kc + tig + 4) * PB + cc]);
                blo[nf][0] = __float_as_uint(sBlo[(kc + tig    ) * PB + cc]);
                blo[nf][1] = __float_as_uint(sBlo[(kc + tig + 4) * PB + cc]);
            }
            #pragma unroll
            for (int mf = 0; mf < 4; mf++)
                #pragma unroll
                for (int nf = 0; nf < 4; nf++) {
                    float* d = acc[mf][nf];
                    mma_tf32(d[0], d[1], d[2], d[3],
                             ahi[mf][0], ahi[mf][1], ahi[mf][2], ahi[mf][3],
                             bhi[nf][0], bhi[nf][1]);
                    mma_tf32(d[0], d[1], d[2], d[3],
                             alo[mf][0], alo[mf][1], alo[mf][2], alo[mf][3],
                             bhi[nf][0], bhi[nf][1]);
                    mma_tf32(d[0], d[1], d[2], d[3],
                             ahi[mf][0], ahi[mf][1], ahi[mf][2], ahi[mf][3],
                             blo[nf][0], blo[nf][1]);
                }
        }
        __syncthreads();
    }

    // Write C.
    #pragma unroll
    for (int mf = 0; mf < 4; mf++) {
        const int r = m0 + wm + mf * 16 + g;
        #pragma unroll
        for (int nf = 0; nf < 4; nf++) {
            const int c = n0 + wn + nf * 8 + 2 * tig;
            float2 v0 = make_float2(acc[mf][nf][0], acc[mf][nf][1]);
            float2 v1 = make_float2(acc[mf][nf][2], acc[mf][nf][3]);
            *(float2*)&C[(size_t)(r    ) * H_DIM + c] = v0;
            *(float2*)&C[(size_t)(r + 8) * H_DIM + c] = v1;
        }
    }
}

// GRU epilogue: combine az/ah with embedding terms, write new_h into h.
__global__ __launch_bounds__(H_DIM) void epi_kernel(
    int t, float* __restrict__ h, const int* __restrict__ x_ids,
    const float* __restrict__ bz, const float* __restrict__ bh) {
    const int e = blockIdx.x;
    const int j = threadIdx.x;
    const int base = 1 + t * E_MSG;
    const int xid = x_ids[t * E_MSG + e];
    size_t o = (size_t)e * H_DIM + j;
    float z  = sigmoidf_(g_az[o] + g_EWz0[xid * H_DIM + j] + bz[j]);
    float ph = tanhf    (g_ah[o] + g_EWh0[xid * H_DIM + j] + bh[j]);
    h[(size_t)(base + e) * H_DIM + j] = (1.f - z) * g_sumh[o] + z * ph;
}

// Root aggregation: relu([emb[root_wid], sum_n h[root_nei]] @ Wo + bo)
__global__ void root_kernel(const float* __restrict__ h, float* __restrict__ out2,
                            const int* __restrict__ root_wid,
                            const int* __restrict__ root_nei,
                            const float* __restrict__ Wo,
                            const float* __restrict__ bo) {
    __shared__ float s_sum[H_DIM];
    int b = blockIdx.x, j = threadIdx.x;
    float sum = 0.f;
    #pragma unroll
    for (int n = 0; n < MAX_NB; n++) {
        int idx = root_nei[b * MAX_NB + n];
        if (idx != 0) sum += h[(size_t)idx * H_DIM + j];
    }
    s_sum[j] = sum;
    __syncthreads();
    float acc = bo[j] + g_EWo0[root_wid[b] * H_DIM + j];
    const float* Wo1 = Wo + H_DIM * H_DIM;
    #pragma unroll 4
    for (int k = 0; k < H_DIM; k++) acc += s_sum[k] * Wo1[k * H_DIM + j];
    out2[b * H_DIM + j] = fmaxf(acc, 0.f);
}

extern "C" void kernel_launch(void* const* d_in, const int* in_sizes, int n_in,
                              void* d_out, int out_size) {
    const int*   x_ids    = (const int*)  d_in[0];
    const int*   nei_idx  = (const int*)  d_in[1];
    const int*   root_wid = (const int*)  d_in[2];
    const int*   root_nei = (const int*)  d_in[3];
    const float* emb      = (const float*)d_in[4];
    const float* Wz       = (const float*)d_in[5];
    const float* bz       = (const float*)d_in[6];
    const float* Wr       = (const float*)d_in[7];
    const float* Ur       = (const float*)d_in[8];
    const float* bur      = (const float*)d_in[9];
    const float* Wh       = (const float*)d_in[10];
    const float* bh       = (const float*)d_in[11];
    const float* Wo       = (const float*)d_in[12];
    const float* bo       = (const float*)d_in[13];

    float* h    = (float*)d_out;                         // [(1+M), H]
    float* out2 = h + (size_t)(1 + M_TOTAL) * H_DIM;     // [B, H]

    zero_kernel<<<1, H_DIM>>>(h);
    precompute_kernel<<<V_VOCAB, H_DIM>>>(emb, Wz, Wr, Wh, Wo);
    bsplit_kernel<<<3 * H_DIM, H_DIM>>>(Wz, Wh, Ur);

    // g_sumh/g_sg base pointers as device symbols accessed inside kernels;
    // mma kernel takes raw pointers, resolved here via the globals' addresses
    // is not allowed host-side, so pass via kernel that reads globals directly:
    // instead we pass device pointers obtained from the globals by a tiny trick:
    // mma kernel's A/C args point into g_* arrays; take their addresses from
    // a device-side perspective using cudaGetSymbolAddress-free approach:
    // since __device__ globals have fixed addresses, capture them with a kernel
    // is overkill — cudaGetSymbolAddress is host API and allowed (no alloc).
    static float *p_sumh = nullptr, *p_sg = nullptr, *p_az = nullptr,
                 *p_ah = nullptr, *p_HU = nullptr;
    if (!p_sumh) {
        cudaGetSymbolAddress((void**)&p_sumh, g_sumh);
        cudaGetSymbolAddress((void**)&p_sg,   g_sg);
        cudaGetSymbolAddress((void**)&p_az,   g_az);
        cudaGetSymbolAddress((void**)&p_ah,   g_ah);
        cudaGetSymbolAddress((void**)&p_HU,   g_HU);
    }

    dim3 gzh(E_MSG / BLK_M, H_DIM / BLK_N, 2);
    dim3 gu (E_MSG / BLK_M, H_DIM / BLK_N, 1);
    for (int t = 0; t < T_DEPTH; t++) {
        const int base = 1 + t * E_MSG;
        gather_kernel<<<E_MSG, H_DIM>>>(t, h, x_ids, nei_idx, bur);
        mma_gemm_kernel<<<gzh, GEMM_THREADS>>>(p_sumh, p_az, 0, p_sg, p_ah, 1);
        epi_kernel<<<E_MSG, H_DIM>>>(t, h, x_ids, bz, bh);
        mma_gemm_kernel<<<gu, GEMM_THREADS>>>(h + (size_t)base * H_DIM,
                                              p_HU + (size_t)base * H_DIM, 2,
                                              h + (size_t)base * H_DIM,
                                              p_HU + (size_t)base * H_DIM, 2);
    }
    root_kernel<<<B_ROOT, H_DIM>>>(h, out2, root_wid, root_nei, Wo, bo);
}

// round 7
// speedup vs baseline: 2.1132x; 1.0962x over previous
#include <cuda_runtime.h>
#include <math.h>
#include <stdint.h>

#define T_DEPTH 12
#define E_MSG   8192
#define H_DIM   256
#define V_VOCAB 800
#define B_ROOT  256
#define MAX_NB  8
#define M_TOTAL (T_DEPTH * E_MSG)

// GEMM tiling: 64x64 block tile, BK=16, 256 threads, 8 warps of 32x16.
#define BM  64
#define BN  64
#define BKK 16
#define PA  20   // sA pitch [m][k]: bank=(4m+k)%32 conflict-free frag reads
#define PB  72   // sB pitch [k][n]: bank=(8k+n)%32 conflict-free frag reads
#define N_ITERS (H_DIM / BKK)   // 16

// Scratch (no cudaMalloc allowed)
__device__ float g_HU[(size_t)(1 + M_TOTAL) * H_DIM];
__device__ float g_EWz0[V_VOCAB * H_DIM];  // emb@Wz0 + bz
__device__ float g_EWr [V_VOCAB * H_DIM];  // emb@Wr + bur
__device__ float g_EWh0[V_VOCAB * H_DIM];  // emb@Wh0 + bh
__device__ float g_EWo0[V_VOCAB * H_DIM];  // emb@Wo0 + bo
__device__ float g_sumh[(size_t)E_MSG * H_DIM];
__device__ float g_sg  [(size_t)E_MSG * H_DIM];
// tf32 hi/lo split of depth-invariant B matrices: [0]=Wz1 [1]=Wh1 [2]=Ur, layout [k][n]
__device__ float g_Bhi[3 * H_DIM * H_DIM];
__device__ float g_Blo[3 * H_DIM * H_DIM];

__device__ __forceinline__ float sigmoidf_(float x) {
    return 1.0f / (1.0f + expf(-x));
}
__device__ __forceinline__ unsigned int tf32_rna(float a) {
    unsigned int r;
    asm("cvt.rna.tf32.f32 %0, %1;" : "=r"(r) : "f"(a));
    return r;
}
__device__ __forceinline__ void mma_tf32(float* d,
                                         unsigned int a0, unsigned int a1,
                                         unsigned int a2, unsigned int a3,
                                         unsigned int b0, unsigned int b1) {
    asm volatile(
        "mma.sync.aligned.m16n8k8.row.col.f32.tf32.tf32.f32 "
        "{%0,%1,%2,%3}, {%4,%5,%6,%7}, {%8,%9}, {%0,%1,%2,%3};"
        : "+f"(d[0]), "+f"(d[1]), "+f"(d[2]), "+f"(d[3])
        : "r"(a0), "r"(a1), "r"(a2), "r"(a3), "r"(b0), "r"(b1));
}
__device__ __forceinline__ void cp_async16(uint32_t saddr, const float* gptr) {
    asm volatile("cp.async.cg.shared.global [%0], [%1], 16;" :: "r"(saddr), "l"(gptr));
}
#define CP_COMMIT()   asm volatile("cp.async.commit_group;")
#define CP_WAIT(n)    asm volatile("cp.async.wait_group %0;" :: "n"(n))

__global__ void zero_kernel(float* __restrict__ h) {
    int j = threadIdx.x;
    h[j] = 0.0f;
    g_HU[j] = 0.0f;
}

// Premultiply embedding by x-side weight blocks; fold biases in.
__global__ void precompute_kernel(const float* __restrict__ emb,
                                  const float* __restrict__ Wz,
                                  const float* __restrict__ Wr,
                                  const float* __restrict__ Wh,
                                  const float* __restrict__ Wo,
                                  const float* __restrict__ bz,
                                  const float* __restrict__ bur,
                                  const float* __restrict__ bh,
                                  const float* __restrict__ bo) {
    __shared__ float se[H_DIM];
    int v = blockIdx.x;
    int j = threadIdx.x;
    se[j] = emb[v * H_DIM + j];
    __syncthreads();
    float az = 0.f, ar = 0.f, ah = 0.f, ao = 0.f;
    #pragma unroll 4
    for (int k = 0; k < H_DIM; k++) {
        float e = se[k];
        az += e * Wz[k * H_DIM + j];
        ar += e * Wr[k * H_DIM + j];
        ah += e * Wh[k * H_DIM + j];
        ao += e * Wo[k * H_DIM + j];
    }
    g_EWz0[v * H_DIM + j] = az + bz[j];
    g_EWr [v * H_DIM + j] = ar + bur[j];
    g_EWh0[v * H_DIM + j] = ah + bh[j];
    g_EWo0[v * H_DIM + j] = ao + bo[j];
}

// Split B matrices (Wz1, Wh1, Ur) into tf32 hi + tf32(residual) tables.
__global__ void bsplit_kernel(const float* __restrict__ Wz,
                              const float* __restrict__ Wh,
                              const float* __restrict__ Ur) {
    int sel = blockIdx.x >> 8;
    int row = blockIdx.x & 255;
    int j   = threadIdx.x;
    const float* src = (sel == 0) ? (Wz + H_DIM * H_DIM)
                     : (sel == 1) ? (Wh + H_DIM * H_DIM) : Ur;
    float w = src[(size_t)row * H_DIM + j];
    unsigned int hi = tf32_rna(w);
    float hif = __uint_as_float(hi);
    unsigned int lo = tf32_rna(w - hif);
    size_t o = (size_t)sel * H_DIM * H_DIM + (size_t)row * H_DIM + j;
    g_Bhi[o] = hif;
    g_Blo[o] = __uint_as_float(lo);
}

// Phase A: neighbor gather. One block per message; thread j = column j.
__global__ __launch_bounds__(H_DIM) void gather_kernel(
    int t, const float* __restrict__ h,
    const int* __restrict__ x_ids, const int* __restrict__ nei_idx) {

    __shared__ int s_nidx[MAX_NB];
    const int e = blockIdx.x;
    const int j = threadIdx.x;

    if (j < MAX_NB)
        s_nidx[j] = nei_idx[((size_t)(t * E_MSG + e)) * MAX_NB + j];
    __syncthreads();

    const int xid = x_ids[t * E_MSG + e];
    const float r1b = g_EWr[xid * H_DIM + j];   // includes bur

    float sum_h = 0.f, sg = 0.f;
    #pragma unroll
    for (int n = 0; n < MAX_NB; n++) {
        int idx = s_nidx[n];
        if (idx != 0) {
            float hn = h[(size_t)idx * H_DIM + j];
            float hu = g_HU[(size_t)idx * H_DIM + j];
            sum_h += hn;
            sg = fmaf(sigmoidf_(r1b + hu), hn, sg);
        }
    }
    g_sumh[(size_t)e * H_DIM + j] = sum_h;
    g_sg  [(size_t)e * H_DIM + j] = sg;
}

// ============================================================================
// Fused dual GEMM (sumh@Wz1, sg@Wh1) + GRU epilogue -> writes h rows.
// 64x64 tile, 256 threads, double-buffered cp.async, 3xTF32 mma.
// ============================================================================
__global__ __launch_bounds__(256) void gemm_zh_epi_kernel(
    int t, float* __restrict__ h,
    const float* __restrict__ sumh, const float* __restrict__ sg,
    const int* __restrict__ x_ids) {

    extern __shared__ float smem[];
    // layout: sA1[2][BM*PA] | sA2[2][BM*PA] | sBz[2][2][BKK*PB] | sBh[2][2][BKK*PB]
    float* sA1 = smem;
    float* sA2 = sA1 + 2 * BM * PA;
    float* sBz = sA2 + 2 * BM * PA;          // [buf*2 + hl][BKK*PB]
    float* sBh = sBz + 4 * BKK * PB;

    const int tid  = threadIdx.x;
    const int lane = tid & 31;
    const int warp = tid >> 5;
    const int wm   = (warp & 1) * 32;
    const int wn   = (warp >> 1) * 16;
    const int g    = lane >> 2;
    const int tig  = lane & 3;
    const int m0   = blockIdx.x * BM;
    const int n0   = blockIdx.y * BN;
    const int tE   = t * E_MSG;
    const int base = 1 + tE;

    const float* Bz_hi = g_Bhi;
    const float* Bz_lo = g_Blo;
    const float* Bh_hi = g_Bhi + H_DIM * H_DIM;
    const float* Bh_lo = g_Blo + H_DIM * H_DIM;

    // staging indices: A: 1 chunk per thread per array; B: 1 chunk per table.
    const int am = tid >> 2, ak = (tid & 3) * 4;
    const int bk = tid >> 4, bn = (tid & 15) * 4;

    auto stage = [&](int buf, int kb) {
        cp_async16((uint32_t)__cvta_generic_to_shared(&sA1[buf * BM * PA + am * PA + ak]),
                   &sumh[(size_t)(m0 + am) * H_DIM + kb + ak]);
        cp_async16((uint32_t)__cvta_generic_to_shared(&sA2[buf * BM * PA + am * PA + ak]),
                   &sg[(size_t)(m0 + am) * H_DIM + kb + ak]);
        size_t bo_ = (size_t)(kb + bk) * H_DIM + n0 + bn;
        cp_async16((uint32_t)__cvta_generic_to_shared(&sBz[(buf * 2 + 0) * BKK * PB + bk * PB + bn]), Bz_hi + bo_);
        cp_async16((uint32_t)__cvta_generic_to_shared(&sBz[(buf * 2 + 1) * BKK * PB + bk * PB + bn]), Bz_lo + bo_);
        cp_async16((uint32_t)__cvta_generic_to_shared(&sBh[(buf * 2 + 0) * BKK * PB + bk * PB + bn]), Bh_hi + bo_);
        cp_async16((uint32_t)__cvta_generic_to_shared(&sBh[(buf * 2 + 1) * BKK * PB + bk * PB + bn]), Bh_lo + bo_);
    };

    float accZ[2][2][4], accH[2][2][4];
    #pragma unroll
    for (int mf = 0; mf < 2; mf++)
        #pragma unroll
        for (int nf = 0; nf < 2; nf++)
            #pragma unroll
            for (int c = 0; c < 4; c++) { accZ[mf][nf][c] = 0.f; accH[mf][nf][c] = 0.f; }

    stage(0, 0);
    CP_COMMIT();
    int buf = 0;
    for (int it = 0; it < N_ITERS; it++) {
        if (it + 1 < N_ITERS) {
            stage(buf ^ 1, (it + 1) * BKK);
            CP_COMMIT();
            CP_WAIT(1);
        } else {
            CP_WAIT(0);
        }
        __syncthreads();

        const float* A1 = sA1 + buf * BM * PA;
        const float* A2 = sA2 + buf * BM * PA;
        const float* BzH = sBz + (buf * 2 + 0) * BKK * PB;
        const float* BzL = sBz + (buf * 2 + 1) * BKK * PB;
        const float* BhH = sBh + (buf * 2 + 0) * BKK * PB;
        const float* BhL = sBh + (buf * 2 + 1) * BKK * PB;

        #pragma unroll
        for (int ks = 0; ks < BKK; ks += 8) {
            // ---- GEMM Z ----
            {
                unsigned int ahi[2][4], alo[2][4];
                #pragma unroll
                for (int mf = 0; mf < 2; mf++) {
                    const int r0 = wm + mf * 16 + g;
                    float a0 = A1[(r0    ) * PA + ks + tig    ];
                    float a1 = A1[(r0 + 8) * PA + ks + tig    ];
                    float a2 = A1[(r0    ) * PA + ks + tig + 4];
                    float a3 = A1[(r0 + 8) * PA + ks + tig + 4];
                    ahi[mf][0] = tf32_rna(a0); alo[mf][0] = tf32_rna(a0 - __uint_as_float(ahi[mf][0]));
                    ahi[mf][1] = tf32_rna(a1); alo[mf][1] = tf32_rna(a1 - __uint_as_float(ahi[mf][1]));
                    ahi[mf][2] = tf32_rna(a2); alo[mf][2] = tf32_rna(a2 - __uint_as_float(ahi[mf][2]));
                    ahi[mf][3] = tf32_rna(a3); alo[mf][3] = tf32_rna(a3 - __uint_as_float(ahi[mf][3]));
                }
                unsigned int bhi[2][2], blo[2][2];
                #pragma unroll
                for (int nf = 0; nf < 2; nf++) {
                    const int cc = wn + nf * 8 + g;
                    bhi[nf][0] = __float_as_uint(BzH[(ks + tig    ) * PB + cc]);
                    bhi[nf][1] = __float_as_uint(BzH[(ks + tig + 4) * PB + cc]);
                    blo[nf][0] = __float_as_uint(BzL[(ks + tig    ) * PB + cc]);
                    blo[nf][1] = __float_as_uint(BzL[(ks + tig + 4) * PB + cc]);
                }
                #pragma unroll
                for (int mf = 0; mf < 2; mf++)
                    #pragma unroll
                    for (int nf = 0; nf < 2; nf++) {
                        mma_tf32(accZ[mf][nf], ahi[mf][0], ahi[mf][1], ahi[mf][2], ahi[mf][3], bhi[nf][0], bhi[nf][1]);
                        mma_tf32(accZ[mf][nf], alo[mf][0], alo[mf][1], alo[mf][2], alo[mf][3], bhi[nf][0], bhi[nf][1]);
                        mma_tf32(accZ[mf][nf], ahi[mf][0], ahi[mf][1], ahi[mf][2], ahi[mf][3], blo[nf][0], blo[nf][1]);
                    }
            }
            // ---- GEMM H ----
            {
                unsigned int ahi[2][4], alo[2][4];
                #pragma unroll
                for (int mf = 0; mf < 2; mf++) {
                    const int r0 = wm + mf * 16 + g;
                    float a0 = A2[(r0    ) * PA + ks + tig    ];
                    float a1 = A2[(r0 + 8) * PA + ks + tig    ];
                    float a2 = A2[(r0    ) * PA + ks + tig + 4];
                    float a3 = A2[(r0 + 8) * PA + ks + tig + 4];
                    ahi[mf][0] = tf32_rna(a0); alo[mf][0] = tf32_rna(a0 - __uint_as_float(ahi[mf][0]));
                    ahi[mf][1] = tf32_rna(a1); alo[mf][1] = tf32_rna(a1 - __uint_as_float(ahi[mf][1]));
                    ahi[mf][2] = tf32_rna(a2); alo[mf][2] = tf32_rna(a2 - __uint_as_float(ahi[mf][2]));
                    ahi[mf][3] = tf32_rna(a3); alo[mf][3] = tf32_rna(a3 - __uint_as_float(ahi[mf][3]));
                }
                unsigned int bhi[2][2], blo[2][2];
                #pragma unroll
                for (int nf = 0; nf < 2; nf++) {
                    const int cc = wn + nf * 8 + g;
                    bhi[nf][0] = __float_as_uint(BhH[(ks + tig    ) * PB + cc]);
                    bhi[nf][1] = __float_as_uint(BhH[(ks + tig + 4) * PB + cc]);
                    blo[nf][0] = __float_as_uint(BhL[(ks + tig    ) * PB + cc]);
                    blo[nf][1] = __float_as_uint(BhL[(ks + tig + 4) * PB + cc]);
                }
                #pragma unroll
                for (int mf = 0; mf < 2; mf++)
                    #pragma unroll
                    for (int nf = 0; nf < 2; nf++) {
                        mma_tf32(accH[mf][nf], ahi[mf][0], ahi[mf][1], ahi[mf][2], ahi[mf][3], bhi[nf][0], bhi[nf][1]);
                        mma_tf32(accH[mf][nf], alo[mf][0], alo[mf][1], alo[mf][2], alo[mf][3], bhi[nf][0], bhi[nf][1]);
                        mma_tf32(accH[mf][nf], ahi[mf][0], ahi[mf][1], ahi[mf][2], ahi[mf][3], blo[nf][0], blo[nf][1]);
                    }
            }
        }
        __syncthreads();
        buf ^= 1;
    }

    // ---- fused GRU epilogue: z = sig(az + EWz0[xid]); ph = tanh(ah + EWh0[xid]) ----
    #pragma unroll
    for (int mf = 0; mf < 2; mf++) {
        #pragma unroll
        for (int hh = 0; hh < 2; hh++) {
            const int row = m0 + wm + mf * 16 + g + hh * 8;
            const int xid = x_ids[tE + row];
            #pragma unroll
            for (int nf = 0; nf < 2; nf++) {
                const int c = n0 + wn + nf * 8 + 2 * tig;
                float az0 = accZ[mf][nf][2 * hh], az1 = accZ[mf][nf][2 * hh + 1];
                float ah0 = accH[mf][nf][2 * hh], ah1 = accH[mf][nf][2 * hh + 1];
                float2 ewz = *(const float2*)&g_EWz0[(size_t)xid * H_DIM + c];
                float2 ewh = *(const float2*)&g_EWh0[(size_t)xid * H_DIM + c];
                float2 sh  = *(const float2*)&sumh[(size_t)row * H_DIM + c];
                float z0 = sigmoidf_(az0 + ewz.x);
                float z1 = sigmoidf_(az1 + ewz.y);
                float p0 = tanhf(ah0 + ewh.x);
                float p1 = tanhf(ah1 + ewh.y);
                float2 out;
                out.x = (1.f - z0) * sh.x + z0 * p0;
                out.y = (1.f - z1) * sh.y + z1 * p1;
                *(float2*)&h[(size_t)(base + row) * H_DIM + c] = out;
            }
        }
    }
}

// ============================================================================
// HU memo GEMM: HU(rows of depth t) = new_h @ Ur. Same pipeline, single GEMM.
// ============================================================================
__global__ __launch_bounds__(256) void gemm_hu_kernel(
    const float* __restrict__ A, float* __restrict__ C) {

    __shared__ float sA[2 * BM * PA];
    __shared__ float sB[4 * BKK * PB];   // [buf*2 + hl]

    const int tid  = threadIdx.x;
    const int lane = tid & 31;
    const int warp = tid >> 5;
    const int wm   = (warp & 1) * 32;
    const int wn   = (warp >> 1) * 16;
    const int g    = lane >> 2;
    const int tig  = lane & 3;
    const int m0   = blockIdx.x * BM;
    const int n0   = blockIdx.y * BN;

    const float* B_hi = g_Bhi + 2 * H_DIM * H_DIM;
    const float* B_lo = g_Blo + 2 * H_DIM * H_DIM;

    const int am = tid >> 2, ak = (tid & 3) * 4;
    const int bk = tid >> 4, bn = (tid & 15) * 4;

    auto stage = [&](int buf, int kb) {
        cp_async16((uint32_t)__cvta_generic_to_shared(&sA[buf * BM * PA + am * PA + ak]),
                   &A[(size_t)(m0 + am) * H_DIM + kb + ak]);
        size_t bo_ = (size_t)(kb + bk) * H_DIM + n0 + bn;
        cp_async16((uint32_t)__cvta_generic_to_shared(&sB[(buf * 2 + 0) * BKK * PB + bk * PB + bn]), B_hi + bo_);
        cp_async16((uint32_t)__cvta_generic_to_shared(&sB[(buf * 2 + 1) * BKK * PB + bk * PB + bn]), B_lo + bo_);
    };

    float acc[2][2][4];
    #pragma unroll
    for (int mf = 0; mf < 2; mf++)
        #pragma unroll
        for (int nf = 0; nf < 2; nf++)
            #pragma unroll
            for (int c = 0; c < 4; c++) acc[mf][nf][c] = 0.f;

    stage(0, 0);
    CP_COMMIT();
    int buf = 0;
    for (int it = 0; it < N_ITERS; it++) {
        if (it + 1 < N_ITERS) {
            stage(buf ^ 1, (it + 1) * BKK);
            CP_COMMIT();
            CP_WAIT(1);
        } else {
            CP_WAIT(0);
        }
        __syncthreads();

        const float* Ab = sA + buf * BM * PA;
        const float* BH = sB + (buf * 2 + 0) * BKK * PB;
        const float* BL = sB + (buf * 2 + 1) * BKK * PB;

        #pragma unroll
        for (int ks = 0; ks < BKK; ks += 8) {
            unsigned int ahi[2][4], alo[2][4];
            #pragma unroll
            for (int mf = 0; mf < 2; mf++) {
                const int r0 = wm + mf * 16 + g;
                float a0 = Ab[(r0    ) * PA + ks + tig    ];
                float a1 = Ab[(r0 + 8) * PA + ks + tig    ];
                float a2 = Ab[(r0    ) * PA + ks + tig + 4];
                float a3 = Ab[(r0 + 8) * PA + ks + tig + 4];
                ahi[mf][0] = tf32_rna(a0); alo[mf][0] = tf32_rna(a0 - __uint_as_float(ahi[mf][0]));
                ahi[mf][1] = tf32_rna(a1); alo[mf][1] = tf32_rna(a1 - __uint_as_float(ahi[mf][1]));
                ahi[mf][2] = tf32_rna(a2); alo[mf][2] = tf32_rna(a2 - __uint_as_float(ahi[mf][2]));
                ahi[mf][3] = tf32_rna(a3); alo[mf][3] = tf32_rna(a3 - __uint_as_float(ahi[mf][3]));
            }
            unsigned int bhi[2][2], blo[2][2];
            #pragma unroll
            for (int nf = 0; nf < 2; nf++) {
                const int cc = wn + nf * 8 + g;
                bhi[nf][0] = __float_as_uint(BH[(ks + tig    ) * PB + cc]);
                bhi[nf][1] = __float_as_uint(BH[(ks + tig + 4) * PB + cc]);
                blo[nf][0] = __float_as_uint(BL[(ks + tig    ) * PB + cc]);
                blo[nf][1] = __float_as_uint(BL[(ks + tig + 4) * PB + cc]);
            }
            #pragma unroll
            for (int mf = 0; mf < 2; mf++)
                #pragma unroll
                for (int nf = 0; nf < 2; nf++) {
                    mma_tf32(acc[mf][nf], ahi[mf][0], ahi[mf][1], ahi[mf][2], ahi[mf][3], bhi[nf][0], bhi[nf][1]);
                    mma_tf32(acc[mf][nf], alo[mf][0], alo[mf][1], alo[mf][2], alo[mf][3], bhi[nf][0], bhi[nf][1]);
                    mma_tf32(acc[mf][nf], ahi[mf][0], ahi[mf][1], ahi[mf][2], ahi[mf][3], blo[nf][0], blo[nf][1]);
                }
        }
        __syncthreads();
        buf ^= 1;
    }

    #pragma unroll
    for (int mf = 0; mf < 2; mf++) {
        const int r = m0 + wm + mf * 16 + g;
        #pragma unroll
        for (int nf = 0; nf < 2; nf++) {
            const int c = n0 + wn + nf * 8 + 2 * tig;
            *(float2*)&C[(size_t)(r    ) * H_DIM + c] = make_float2(acc[mf][nf][0], acc[mf][nf][1]);
            *(float2*)&C[(size_t)(r + 8) * H_DIM + c] = make_float2(acc[mf][nf][2], acc[mf][nf][3]);
        }
    }
}

// Root aggregation: relu([emb[root_wid], sum_n h[root_nei]] @ Wo + bo)
__global__ void root_kernel(const float* __restrict__ h, float* __restrict__ out2,
                            const int* __restrict__ root_wid,
                            const int* __restrict__ root_nei,
                            const float* __restrict__ Wo) {
    __shared__ float s_sum[H_DIM];
    int b = blockIdx.x, j = threadIdx.x;
    float sum = 0.f;
    #pragma unroll
    for (int n = 0; n < MAX_NB; n++) {
        int idx = root_nei[b * MAX_NB + n];
        if (idx != 0) sum += h[(size_t)idx * H_DIM + j];
    }
    s_sum[j] = sum;
    __syncthreads();
    float acc = g_EWo0[root_wid[b] * H_DIM + j];   // includes bo
    const float* Wo1 = Wo + H_DIM * H_DIM;
    #pragma unroll 4
    for (int k = 0; k < H_DIM; k++) acc += s_sum[k] * Wo1[k * H_DIM + j];
    out2[b * H_DIM + j] = fmaxf(acc, 0.f);
}

extern "C" void kernel_launch(void* const* d_in, const int* in_sizes, int n_in,
                              void* d_out, int out_size) {
    const int*   x_ids    = (const int*)  d_in[0];
    const int*   nei_idx  = (const int*)  d_in[1];
    const int*   root_wid = (const int*)  d_in[2];
    const int*   root_nei = (const int*)  d_in[3];
    const float* emb      = (const float*)d_in[4];
    const float* Wz       = (const float*)d_in[5];
    const float* bz       = (const float*)d_in[6];
    const float* Wr       = (const float*)d_in[7];
    const float* Ur       = (const float*)d_in[8];
    const float* bur      = (const float*)d_in[9];
    const float* Wh       = (const float*)d_in[10];
    const float* bh       = (const float*)d_in[11];
    const float* Wo       = (const float*)d_in[12];
    const float* bo       = (const float*)d_in[13];

    float* h    = (float*)d_out;                         // [(1+M), H]
    float* out2 = h + (size_t)(1 + M_TOTAL) * H_DIM;     // [B, H]

    float *p_sumh, *p_sg, *p_HU;
    cudaGetSymbolAddress((void**)&p_sumh, g_sumh);
    cudaGetSymbolAddress((void**)&p_sg,   g_sg);
    cudaGetSymbolAddress((void**)&p_HU,   g_HU);

    const int dual_smem = (2 * 2 * BM * PA + 2 * 4 * BKK * PB) * (int)sizeof(float);
    cudaFuncSetAttribute(gemm_zh_epi_kernel,
                         cudaFuncAttributeMaxDynamicSharedMemorySize, dual_smem);

    zero_kernel<<<1, H_DIM>>>(h);
    precompute_kernel<<<V_VOCAB, H_DIM>>>(emb, Wz, Wr, Wh, Wo, bz, bur, bh, bo);
    bsplit_kernel<<<3 * H_DIM, H_DIM>>>(Wz, Wh, Ur);

    dim3 ggrid(E_MSG / BM, H_DIM / BN);
    for (int t = 0; t < T_DEPTH; t++) {
        const size_t base = (size_t)(1 + t * E_MSG) * H_DIM;
        gather_kernel<<<E_MSG, H_DIM>>>(t, h, x_ids, nei_idx);
        gemm_zh_epi_kernel<<<ggrid, 256, dual_smem>>>(t, h, p_sumh, p_sg, x_ids);
        gemm_hu_kernel<<<ggrid, 256>>>(h + base, p_HU + base);
    }
    root_kernel<<<B_ROOT, H_DIM>>>(h, out2, root_wid, root_nei, Wo);
}